// round 16
// baseline (speedup 1.0000x reference)
#include <cuda_runtime.h>
#include <cuda_bf16.h>
#include <stdint.h>
#include <math.h>

// Problem dims (fixed)
#define TKN 32768        // B*S
#define DIM 768
#define HID 2048
#define N1  4096         // 2H

// ---------------- scratch ----------------
__device__ __align__(256) double g_acc[2];
__device__ __align__(256) float  g_wdq[2];
__device__ __align__(256) int8_t g_xq[(size_t)TKN * DIM];
__device__ __align__(256) float  g_xdq[TKN];
__device__ __align__(256) int8_t g_w1q[(size_t)N1 * DIM];
__device__ __align__(256) int8_t g_w2q[(size_t)DIM * HID];
__device__ __align__(256) float  g_y[(size_t)TKN * HID];   // fp32 (fp16 broke accuracy in R9)
__device__ __align__(256) int8_t g_yq[(size_t)TKN * HID];
__device__ __align__(256) float  g_ydq[TKN];

// ---------------- helpers ----------------
__device__ __forceinline__ uint32_t smem_u32(const void* p) {
    return (uint32_t)__cvta_generic_to_shared(p);
}
__device__ __forceinline__ void cp16(uint32_t s, const void* g) {
    asm volatile("cp.async.cg.shared.global [%0], [%1], 16;" :: "r"(s), "l"(g));
}
__device__ __forceinline__ void cp_commit() { asm volatile("cp.async.commit_group;"); }
template <int N> __device__ __forceinline__ void cp_wait() {
    asm volatile("cp.async.wait_group %0;" :: "n"(N));
}
__device__ __forceinline__ void mma_s8(int* c, int a0, int a1, int a2, int a3,
                                       int b0, int b1) {
    asm volatile(
        "mma.sync.aligned.m16n8k32.row.col.s32.s8.s8.s32 "
        "{%0,%1,%2,%3}, {%4,%5,%6,%7}, {%8,%9}, {%0,%1,%2,%3};"
        : "+r"(c[0]), "+r"(c[1]), "+r"(c[2]), "+r"(c[3])
        : "r"(a0), "r"(a1), "r"(a2), "r"(a3), "r"(b0), "r"(b1));
}

// ---------------- warp reductions ----------------
__device__ __forceinline__ float warpSum(float v) {
#pragma unroll
    for (int o = 16; o; o >>= 1) v += __shfl_xor_sync(0xffffffffu, v, o);
    return v;
}
__device__ __forceinline__ float warpMax(float v) {
#pragma unroll
    for (int o = 16; o; o >>= 1) v = fmaxf(v, __shfl_xor_sync(0xffffffffu, v, o));
    return v;
}

// ---------------- weight quantization ----------------
__global__ void k_init() { g_acc[0] = 0.0; g_acc[1] = 0.0; }

__global__ void k_abssum(const float* __restrict__ w, int n, int idx) {
    double s = 0.0;
    for (int i = blockIdx.x * blockDim.x + threadIdx.x; i < n; i += gridDim.x * blockDim.x)
        s += (double)fabsf(w[i]);
#pragma unroll
    for (int o = 16; o; o >>= 1) s += __shfl_down_sync(0xffffffffu, s, o);
    __shared__ double sm[8];
    int lane = threadIdx.x & 31, wid = threadIdx.x >> 5;
    if (lane == 0) sm[wid] = s;
    __syncthreads();
    if (wid == 0) {
        s = (lane < (int)(blockDim.x >> 5)) ? sm[lane] : 0.0;
#pragma unroll
        for (int o = 4; o; o >>= 1) s += __shfl_down_sync(0xffffffffu, s, o);
        if (lane == 0) atomicAdd(&g_acc[idx], s);
    }
}

// destination selected device-side (host must never pass __device__ symbols)
__global__ void k_wquant(const float* __restrict__ w, int n4, int idx, double inv_n) {
    int8_t* __restrict__ q = (idx == 0) ? g_w1q : g_w2q;
    float mean = (float)(g_acc[idx] * inv_n);
    float scale = 1.0f / fmaxf(mean, 1e-5f);
    int i = blockIdx.x * blockDim.x + threadIdx.x;
    if (i < n4) {
        float4 v = ((const float4*)w)[i];
        char4 c;
        c.x = (char)max(-1, min(1, (int)rintf(v.x * scale)));
        c.y = (char)max(-1, min(1, (int)rintf(v.y * scale)));
        c.z = (char)max(-1, min(1, (int)rintf(v.z * scale)));
        c.w = (char)max(-1, min(1, (int)rintf(v.w * scale)));
        ((char4*)q)[i] = c;
    }
    if (i == 0) g_wdq[idx] = 1.0f / scale;
}

// ---------------- warp-per-token rmsnorm + int8 quant (no barriers) ----------------
__global__ void __launch_bounds__(256) k_quant_x(const float* __restrict__ x,
                                                 const float* __restrict__ gain) {
    int t = blockIdx.x * 8 + (threadIdx.x >> 5);
    int lane = threadIdx.x & 31;
    const float4* row = (const float4*)(x + (size_t)t * DIM);
    const float4* grow = (const float4*)gain;
    float4 v[6];
    float ss = 0.0f;
#pragma unroll
    for (int i = 0; i < 6; i++) {
        v[i] = row[lane + 32 * i];
        ss += v[i].x * v[i].x + v[i].y * v[i].y + v[i].z * v[i].z + v[i].w * v[i].w;
    }
    ss = warpSum(ss);
    float mn = ss / (float)DIM + 1e-6f;
    float rs = (float)(1.0 / sqrt((double)mn));
    float4 nv[6];
    float am = 0.0f;
#pragma unroll
    for (int i = 0; i < 6; i++) {
        float4 g = grow[lane + 32 * i];
        nv[i] = make_float4((v[i].x * rs) * g.x, (v[i].y * rs) * g.y,
                            (v[i].z * rs) * g.z, (v[i].w * rs) * g.w);
        am = fmaxf(am, fmaxf(fmaxf(fabsf(nv[i].x), fabsf(nv[i].y)),
                             fmaxf(fabsf(nv[i].z), fabsf(nv[i].w))));
    }
    am = warpMax(am);
    float scale = 127.0f / fmaxf(am, 1e-5f);
    char4* qrow = (char4*)(g_xq + (size_t)t * DIM);
#pragma unroll
    for (int i = 0; i < 6; i++) {
        char4 c;
        c.x = (char)max(-128, min(127, (int)rintf(nv[i].x * scale)));
        c.y = (char)max(-128, min(127, (int)rintf(nv[i].y * scale)));
        c.z = (char)max(-128, min(127, (int)rintf(nv[i].z * scale)));
        c.w = (char)max(-128, min(127, (int)rintf(nv[i].w * scale)));
        qrow[lane + 32 * i] = c;
    }
    if (lane == 0) g_xdq[t] = 1.0f / scale;
}

__global__ void __launch_bounds__(256) k_quant_y(const float* __restrict__ gain) {
    int t = blockIdx.x * 8 + (threadIdx.x >> 5);
    int lane = threadIdx.x & 31;
    const float4* row = (const float4*)(g_y + (size_t)t * HID);
    const float4* grow = (const float4*)gain;
    float4 v[16];
    float ss = 0.0f;
#pragma unroll
    for (int i = 0; i < 16; i++) {
        v[i] = row[lane + 32 * i];
        ss += v[i].x * v[i].x + v[i].y * v[i].y + v[i].z * v[i].z + v[i].w * v[i].w;
    }
    ss = warpSum(ss);
    float mn = ss / (float)HID + 1e-6f;
    float rs = (float)(1.0 / sqrt((double)mn));
    float am = 0.0f;
#pragma unroll
    for (int i = 0; i < 16; i++) {
        float4 g = grow[lane + 32 * i];
        float4 nv = make_float4((v[i].x * rs) * g.x, (v[i].y * rs) * g.y,
                                (v[i].z * rs) * g.z, (v[i].w * rs) * g.w);
        am = fmaxf(am, fmaxf(fmaxf(fabsf(nv.x), fabsf(nv.y)),
                             fmaxf(fabsf(nv.z), fabsf(nv.w))));
    }
    am = warpMax(am);
    float scale = 127.0f / fmaxf(am, 1e-5f);
    char4* qrow = (char4*)(g_yq + (size_t)t * HID);
#pragma unroll
    for (int i = 0; i < 16; i++) {
        float4 g = grow[lane + 32 * i];
        float4 nv = make_float4((v[i].x * rs) * g.x, (v[i].y * rs) * g.y,
                                (v[i].z * rs) * g.z, (v[i].w * rs) * g.w);
        char4 c;
        c.x = (char)max(-128, min(127, (int)rintf(nv.x * scale)));
        c.y = (char)max(-128, min(127, (int)rintf(nv.y * scale)));
        c.z = (char)max(-128, min(127, (int)rintf(nv.z * scale)));
        c.w = (char)max(-128, min(127, (int)rintf(nv.w * scale)));
        qrow[lane + 32 * i] = c;
    }
    if (lane == 0) g_ydq[t] = 1.0f / scale;
}

// ---------------- tensor-core GEMMs: 3-stage cp.async, ONE sync per iter ----------------
// Shared row stride: 64 data bytes + 16 pad = 80 B = 20 ints (conflict-free).
#define ASTR 20
#define BUFI 2560            // ints per tile (128 rows * 20)
#define SSTG (2 * BUFI)      // ints per stage (A + B)
#define GSM  (3 * SSTG * 4)  // 61440 bytes dynamic smem

// GEMM1: h = xq @ w1q^T; block 128m x (64 up + 64 gate); 4 warps 2x2.
__global__ void __launch_bounds__(128) k_gemm1() {
    extern __shared__ int sh[];
    const int8_t* __restrict__ xq = g_xq;
    const int8_t* __restrict__ wq = g_w1q;
    int m0 = blockIdx.y << 7;
    int n0 = blockIdx.x << 6;
    int tid = threadIdx.x, lane = tid & 31, wid = tid >> 5;
    int wm = wid >> 1, wn = wid & 1;

    int acc[4][8][4];                      // [mt][nt: 0-3 up, 4-7 gate][c]
#pragma unroll
    for (int i = 0; i < 4; i++)
#pragma unroll
        for (int j = 0; j < 8; j++)
#pragma unroll
            for (int c = 0; c < 4; c++) acc[i][j][c] = 0;

#define G1_LOAD(IT, BI)                                                         \
    {                                                                           \
        int k0 = (IT) * 64;                                                     \
        int* Ab = sh + (BI) * SSTG;                                             \
        int* Bb = Ab + BUFI;                                                    \
        _Pragma("unroll")                                                       \
        for (int c = tid; c < 512; c += 128) {                                  \
            int r = c >> 2, ck = c & 3;                                         \
            cp16(smem_u32(Ab + r * ASTR + ck * 4),                              \
                 xq + (size_t)(m0 + r) * DIM + k0 + ck * 16);                   \
            int nr = (r < 64) ? (n0 + r) : (HID + n0 + r - 64);                 \
            cp16(smem_u32(Bb + r * ASTR + ck * 4),                              \
                 wq + (size_t)nr * DIM + k0 + ck * 16);                         \
        }                                                                       \
    }

    G1_LOAD(0, 0); cp_commit();
    G1_LOAD(1, 1); cp_commit();
    int bi = 0;                 // it % 3
#pragma unroll 1
    for (int it = 0; it < 12; it++) {
        if (it < 11) cp_wait<1>(); else cp_wait<0>();
        __syncthreads();        // single barrier per iter (3-stage makes 2nd redundant)
        if (it + 2 < 12) {
            int nb = bi + 2; if (nb >= 3) nb -= 3;
            G1_LOAD(it + 2, nb); cp_commit();
        }
        int* Ab = sh + bi * SSTG;
        int* Bb = Ab + BUFI;
#pragma unroll
        for (int ks = 0; ks < 2; ks++) {
            int w = ks * 8 + (lane & 3);
            int a[4][4];
#pragma unroll
            for (int mt = 0; mt < 4; mt++) {
                int r = wm * 64 + mt * 16 + (lane >> 2);
                a[mt][0] = Ab[r * ASTR + w];
                a[mt][1] = Ab[(r + 8) * ASTR + w];
                a[mt][2] = Ab[r * ASTR + w + 4];
                a[mt][3] = Ab[(r + 8) * ASTR + w + 4];
            }
#pragma unroll
            for (int nt = 0; nt < 8; nt++) {
                int rn = ((nt < 4) ? (wn * 32 + nt * 8) : (64 + wn * 32 + (nt - 4) * 8))
                         + (lane >> 2);
                int b0 = Bb[rn * ASTR + w];
                int b1 = Bb[rn * ASTR + w + 4];
#pragma unroll
                for (int mt = 0; mt < 4; mt++)
                    mma_s8(acc[mt][nt], a[mt][0], a[mt][1], a[mt][2], a[mt][3], b0, b1);
            }
        }
        if (++bi == 3) bi = 0;
    }
#undef G1_LOAD

    // epilogue: swiglu + scale, write fp32 y
    float wdq = g_wdq[0];
#pragma unroll
    for (int mt = 0; mt < 4; mt++) {
        int r0 = m0 + wm * 64 + mt * 16 + (lane >> 2);
        float s0 = g_xdq[r0] * wdq;
        float s1 = g_xdq[r0 + 8] * wdq;
#pragma unroll
        for (int nt = 0; nt < 4; nt++) {
            int c = n0 + wn * 32 + nt * 8 + 2 * (lane & 3);
            int* u = acc[mt][nt];
            int* g = acc[mt][nt + 4];
            {
                float up0 = (float)u[0] * s0, gt0 = (float)g[0] * s0;
                float up1 = (float)u[1] * s0, gt1 = (float)g[1] * s0;
                float2 o;
                o.x = gt0 / (1.0f + expf(-gt0)) * up0;
                o.y = gt1 / (1.0f + expf(-gt1)) * up1;
                *(float2*)&g_y[(size_t)r0 * HID + c] = o;
            }
            {
                float up0 = (float)u[2] * s1, gt0 = (float)g[2] * s1;
                float up1 = (float)u[3] * s1, gt1 = (float)g[3] * s1;
                float2 o;
                o.x = gt0 / (1.0f + expf(-gt0)) * up0;
                o.y = gt1 / (1.0f + expf(-gt1)) * up1;
                *(float2*)&g_y[(size_t)(r0 + 8) * HID + c] = o;
            }
        }
    }
}

// GEMM2: out = yq @ w2q^T. Block 128x128, warps 2x2, warp 64x64.
__global__ void __launch_bounds__(128) k_gemm2(float* __restrict__ out) {
    extern __shared__ int sh[];
    const int8_t* __restrict__ yq = g_yq;
    const int8_t* __restrict__ wq = g_w2q;
    int m0 = blockIdx.y << 7;
    int n0 = blockIdx.x << 7;
    int tid = threadIdx.x, lane = tid & 31, wid = tid >> 5;
    int wm = wid >> 1, wn = wid & 1;

    int acc[4][8][4];
#pragma unroll
    for (int i = 0; i < 4; i++)
#pragma unroll
        for (int j = 0; j < 8; j++)
#pragma unroll
            for (int c = 0; c < 4; c++) acc[i][j][c] = 0;

#define G2_LOAD(IT, BI)                                                         \
    {                                                                           \
        int k0 = (IT) * 64;                                                     \
        int* Ab = sh + (BI) * SSTG;                                             \
        int* Bb = Ab + BUFI;                                                    \
        _Pragma("unroll")                                                       \
        for (int c = tid; c < 512; c += 128) {                                  \
            int r = c >> 2, ck = c & 3;                                         \
            cp16(smem_u32(Ab + r * ASTR + ck * 4),                              \
                 yq + (size_t)(m0 + r) * HID + k0 + ck * 16);                   \
            cp16(smem_u32(Bb + r * ASTR + ck * 4),                              \
                 wq + (size_t)(n0 + r) * HID + k0 + ck * 16);                   \
        }                                                                       \
    }

    G2_LOAD(0, 0); cp_commit();
    G2_LOAD(1, 1); cp_commit();
    int bi = 0;
#pragma unroll 1
    for (int it = 0; it < 32; it++) {
        if (it < 31) cp_wait<1>(); else cp_wait<0>();
        __syncthreads();
        if (it + 2 < 32) {
            int nb = bi + 2; if (nb >= 3) nb -= 3;
            G2_LOAD(it + 2, nb); cp_commit();
        }
        int* Ab = sh + bi * SSTG;
        int* Bb = Ab + BUFI;
#pragma unroll
        for (int ks = 0; ks < 2; ks++) {
            int w = ks * 8 + (lane & 3);
            int a[4][4];
#pragma unroll
            for (int mt = 0; mt < 4; mt++) {
                int r = wm * 64 + mt * 16 + (lane >> 2);
                a[mt][0] = Ab[r * ASTR + w];
                a[mt][1] = Ab[(r + 8) * ASTR + w];
                a[mt][2] = Ab[r * ASTR + w + 4];
                a[mt][3] = Ab[(r + 8) * ASTR + w + 4];
            }
#pragma unroll
            for (int nt = 0; nt < 8; nt++) {
                int rn = wn * 64 + nt * 8 + (lane >> 2);
                int b0 = Bb[rn * ASTR + w];
                int b1 = Bb[rn * ASTR + w + 4];
#pragma unroll
                for (int mt = 0; mt < 4; mt++)
                    mma_s8(acc[mt][nt], a[mt][0], a[mt][1], a[mt][2], a[mt][3], b0, b1);
            }
        }
        if (++bi == 3) bi = 0;
    }
#undef G2_LOAD

    float wdq = g_wdq[1];
#pragma unroll
    for (int mt = 0; mt < 4; mt++) {
        int r0 = m0 + wm * 64 + mt * 16 + (lane >> 2);
        float s0 = g_ydq[r0] * wdq;
        float s1 = g_ydq[r0 + 8] * wdq;
#pragma unroll
        for (int nt = 0; nt < 8; nt++) {
            int c = n0 + wn * 64 + nt * 8 + 2 * (lane & 3);
            int* q = acc[mt][nt];
            float2 o0 = make_float2((float)q[0] * s0, (float)q[1] * s0);
            float2 o1 = make_float2((float)q[2] * s1, (float)q[3] * s1);
            *(float2*)&out[(size_t)r0 * DIM + c] = o0;
            *(float2*)&out[(size_t)(r0 + 8) * DIM + c] = o1;
        }
    }
}

// ---------------- eager init: absorb first-launch driver pool growth ----------------
namespace {
struct EagerInit {
    EagerInit() {
        cudaFree(0);
        cudaFuncSetAttribute(k_gemm1, cudaFuncAttributeMaxDynamicSharedMemorySize, GSM);
        cudaFuncSetAttribute(k_gemm2, cudaFuncAttributeMaxDynamicSharedMemorySize, GSM);
        void* py = nullptr; void* pdq = nullptr;
        cudaGetSymbolAddress(&py, g_y);
        cudaGetSymbolAddress(&pdq, g_xdq);
        const float* fy = (const float*)py;
        k_init<<<1, 1>>>();
        k_abssum<<<2, 256>>>(fy, 1024, 0);
        k_wquant<<<1, 256>>>(fy, 256, 0, 1.0);
        k_quant_x<<<1, 256>>>(fy, (const float*)pdq);
        k_quant_y<<<1, 256>>>((const float*)pdq);
        k_gemm1<<<dim3(1, 1), 128, GSM>>>();
        k_gemm2<<<dim3(1, 1), 128, GSM>>>((float*)py);
        cudaDeviceSynchronize();
        cudaGetLastError();
    }
};
EagerInit eager_init_;
}  // namespace

// ---------------- launch ----------------
extern "C" void kernel_launch(void* const* d_in, const int* in_sizes, int n_in,
                              void* d_out, int out_size) {
    const float* x = nullptr, *w_in = nullptr, *gin = nullptr,
               *w_out = nullptr, *gout = nullptr;
    for (int i = 0; i < n_in; i++) {
        long long s = in_sizes[i];
        if (s == 25165824LL || s == 100663296LL)      x     = (const float*)d_in[i];
        else if (s == 3145728LL || s == 12582912LL)   w_in  = (const float*)d_in[i];
        else if (s == 1572864LL || s == 6291456LL)    w_out = (const float*)d_in[i];
        else if (s == 768LL     || s == 3072LL)       gin   = (const float*)d_in[i];
        else if (s == 2048LL    || s == 8192LL)       gout  = (const float*)d_in[i];
    }
    if (!x || !w_in || !gin || !w_out || !gout) {
        int idx[16];
        int m = n_in < 16 ? n_in : 16;
        for (int i = 0; i < m; i++) idx[i] = i;
        for (int a = 0; a < m; a++)
            for (int b = a + 1; b < m; b++)
                if ((long long)in_sizes[idx[b]] < (long long)in_sizes[idx[a]]) {
                    int t = idx[a]; idx[a] = idx[b]; idx[b] = t;
                }
        gin   = (const float*)d_in[idx[0]];
        gout  = (const float*)d_in[idx[1]];
        w_out = (const float*)d_in[idx[2]];
        w_in  = (const float*)d_in[idx[3]];
        x     = (const float*)d_in[idx[4]];
    }
    float* out = (float*)d_out;

    k_init<<<1, 1>>>();
    k_abssum<<<512, 256>>>(w_in,  N1 * DIM, 0);
    k_abssum<<<512, 256>>>(w_out, DIM * HID, 1);

    k_wquant<<<(N1 * DIM / 4 + 255) / 256, 256>>>(w_in,  N1 * DIM / 4, 0,
                                                  1.0 / (double)(N1 * DIM));
    k_wquant<<<(DIM * HID / 4 + 255) / 256, 256>>>(w_out, DIM * HID / 4, 1,
                                                   1.0 / (double)(DIM * HID));

    k_quant_x<<<TKN / 8, 256>>>(x, gin);          // warp-per-token

    k_gemm1<<<dim3(HID / 64, TKN / 128), 128, GSM>>>();

    k_quant_y<<<TKN / 8, 256>>>(gout);            // warp-per-token

    k_gemm2<<<dim3(DIM / 128, TKN / 128), 128, GSM>>>(out);
}

// round 17
// speedup vs baseline: 1.1703x; 1.1703x over previous
#include <cuda_runtime.h>
#include <cuda_bf16.h>
#include <stdint.h>
#include <math.h>

// Problem dims (fixed)
#define TKN 32768        // B*S
#define DIM 768
#define HID 2048
#define N1  4096         // 2H

// ---------------- scratch ----------------
__device__ __align__(256) double g_acc[2];
__device__ __align__(256) float  g_wdq[2];
__device__ __align__(256) int8_t g_xq[(size_t)TKN * DIM];
__device__ __align__(256) float  g_xdq[TKN];
__device__ __align__(256) int8_t g_w1q[(size_t)N1 * DIM];
__device__ __align__(256) int8_t g_w2q[(size_t)DIM * HID];
__device__ __align__(256) float  g_y[(size_t)TKN * HID];   // fp32 (fp16 broke accuracy in R9)
__device__ __align__(256) int8_t g_yq[(size_t)TKN * HID];
__device__ __align__(256) float  g_ydq[TKN];

// ---------------- helpers ----------------
__device__ __forceinline__ uint32_t smem_u32(const void* p) {
    return (uint32_t)__cvta_generic_to_shared(p);
}
__device__ __forceinline__ void cp16(uint32_t s, const void* g) {
    asm volatile("cp.async.cg.shared.global [%0], [%1], 16;" :: "r"(s), "l"(g));
}
__device__ __forceinline__ void cp_commit() { asm volatile("cp.async.commit_group;"); }
template <int N> __device__ __forceinline__ void cp_wait() {
    asm volatile("cp.async.wait_group %0;" :: "n"(N));
}
__device__ __forceinline__ void mma_s8(int* c, int a0, int a1, int a2, int a3,
                                       int b0, int b1) {
    asm volatile(
        "mma.sync.aligned.m16n8k32.row.col.s32.s8.s8.s32 "
        "{%0,%1,%2,%3}, {%4,%5,%6,%7}, {%8,%9}, {%0,%1,%2,%3};"
        : "+r"(c[0]), "+r"(c[1]), "+r"(c[2]), "+r"(c[3])
        : "r"(a0), "r"(a1), "r"(a2), "r"(a3), "r"(b0), "r"(b1));
}

// ---------------- warp reductions ----------------
__device__ __forceinline__ float warpSum(float v) {
#pragma unroll
    for (int o = 16; o; o >>= 1) v += __shfl_xor_sync(0xffffffffu, v, o);
    return v;
}
__device__ __forceinline__ float warpMax(float v) {
#pragma unroll
    for (int o = 16; o; o >>= 1) v = fmaxf(v, __shfl_xor_sync(0xffffffffu, v, o));
    return v;
}

// ---------------- weight quantization ----------------
__global__ void k_init() { g_acc[0] = 0.0; g_acc[1] = 0.0; }

__global__ void k_abssum(const float* __restrict__ w, int n, int idx) {
    double s = 0.0;
    for (int i = blockIdx.x * blockDim.x + threadIdx.x; i < n; i += gridDim.x * blockDim.x)
        s += (double)fabsf(w[i]);
#pragma unroll
    for (int o = 16; o; o >>= 1) s += __shfl_down_sync(0xffffffffu, s, o);
    __shared__ double sm[8];
    int lane = threadIdx.x & 31, wid = threadIdx.x >> 5;
    if (lane == 0) sm[wid] = s;
    __syncthreads();
    if (wid == 0) {
        s = (lane < (int)(blockDim.x >> 5)) ? sm[lane] : 0.0;
#pragma unroll
        for (int o = 4; o; o >>= 1) s += __shfl_down_sync(0xffffffffu, s, o);
        if (lane == 0) atomicAdd(&g_acc[idx], s);
    }
}

// destination selected device-side (host must never pass __device__ symbols)
__global__ void k_wquant(const float* __restrict__ w, int n4, int idx, double inv_n) {
    int8_t* __restrict__ q = (idx == 0) ? g_w1q : g_w2q;
    float mean = (float)(g_acc[idx] * inv_n);
    float scale = 1.0f / fmaxf(mean, 1e-5f);
    int i = blockIdx.x * blockDim.x + threadIdx.x;
    if (i < n4) {
        float4 v = ((const float4*)w)[i];
        char4 c;
        c.x = (char)max(-1, min(1, (int)rintf(v.x * scale)));
        c.y = (char)max(-1, min(1, (int)rintf(v.y * scale)));
        c.z = (char)max(-1, min(1, (int)rintf(v.z * scale)));
        c.w = (char)max(-1, min(1, (int)rintf(v.w * scale)));
        ((char4*)q)[i] = c;
    }
    if (i == 0) g_wdq[idx] = 1.0f / scale;
}

// ---------------- warp-per-token rmsnorm + int8 quant (no barriers) ----------------
__global__ void __launch_bounds__(256) k_quant_x(const float* __restrict__ x,
                                                 const float* __restrict__ gain) {
    int t = blockIdx.x * 8 + (threadIdx.x >> 5);
    int lane = threadIdx.x & 31;
    const float4* row = (const float4*)(x + (size_t)t * DIM);
    const float4* grow = (const float4*)gain;
    float4 v[6];
    float ss = 0.0f;
#pragma unroll
    for (int i = 0; i < 6; i++) {
        v[i] = row[lane + 32 * i];
        ss += v[i].x * v[i].x + v[i].y * v[i].y + v[i].z * v[i].z + v[i].w * v[i].w;
    }
    ss = warpSum(ss);
    float mn = ss / (float)DIM + 1e-6f;
    float rs = (float)(1.0 / sqrt((double)mn));
    float4 nv[6];
    float am = 0.0f;
#pragma unroll
    for (int i = 0; i < 6; i++) {
        float4 g = grow[lane + 32 * i];
        nv[i] = make_float4((v[i].x * rs) * g.x, (v[i].y * rs) * g.y,
                            (v[i].z * rs) * g.z, (v[i].w * rs) * g.w);
        am = fmaxf(am, fmaxf(fmaxf(fabsf(nv[i].x), fabsf(nv[i].y)),
                             fmaxf(fabsf(nv[i].z), fabsf(nv[i].w))));
    }
    am = warpMax(am);
    float scale = 127.0f / fmaxf(am, 1e-5f);
    char4* qrow = (char4*)(g_xq + (size_t)t * DIM);
#pragma unroll
    for (int i = 0; i < 6; i++) {
        char4 c;
        c.x = (char)max(-128, min(127, (int)rintf(nv[i].x * scale)));
        c.y = (char)max(-128, min(127, (int)rintf(nv[i].y * scale)));
        c.z = (char)max(-128, min(127, (int)rintf(nv[i].z * scale)));
        c.w = (char)max(-128, min(127, (int)rintf(nv[i].w * scale)));
        qrow[lane + 32 * i] = c;
    }
    if (lane == 0) g_xdq[t] = 1.0f / scale;
}

__global__ void __launch_bounds__(256) k_quant_y(const float* __restrict__ gain) {
    int t = blockIdx.x * 8 + (threadIdx.x >> 5);
    int lane = threadIdx.x & 31;
    const float4* row = (const float4*)(g_y + (size_t)t * HID);
    const float4* grow = (const float4*)gain;
    float4 v[16];
    float ss = 0.0f;
#pragma unroll
    for (int i = 0; i < 16; i++) {
        v[i] = row[lane + 32 * i];
        ss += v[i].x * v[i].x + v[i].y * v[i].y + v[i].z * v[i].z + v[i].w * v[i].w;
    }
    ss = warpSum(ss);
    float mn = ss / (float)HID + 1e-6f;
    float rs = (float)(1.0 / sqrt((double)mn));
    float am = 0.0f;
#pragma unroll
    for (int i = 0; i < 16; i++) {
        float4 g = grow[lane + 32 * i];
        float4 nv = make_float4((v[i].x * rs) * g.x, (v[i].y * rs) * g.y,
                                (v[i].z * rs) * g.z, (v[i].w * rs) * g.w);
        am = fmaxf(am, fmaxf(fmaxf(fabsf(nv.x), fabsf(nv.y)),
                             fmaxf(fabsf(nv.z), fabsf(nv.w))));
    }
    am = warpMax(am);
    float scale = 127.0f / fmaxf(am, 1e-5f);
    char4* qrow = (char4*)(g_yq + (size_t)t * HID);
#pragma unroll
    for (int i = 0; i < 16; i++) {
        float4 g = grow[lane + 32 * i];
        float4 nv = make_float4((v[i].x * rs) * g.x, (v[i].y * rs) * g.y,
                                (v[i].z * rs) * g.z, (v[i].w * rs) * g.w);
        char4 c;
        c.x = (char)max(-128, min(127, (int)rintf(nv.x * scale)));
        c.y = (char)max(-128, min(127, (int)rintf(nv.y * scale)));
        c.z = (char)max(-128, min(127, (int)rintf(nv.z * scale)));
        c.w = (char)max(-128, min(127, (int)rintf(nv.w * scale)));
        qrow[lane + 32 * i] = c;
    }
    if (lane == 0) g_ydq[t] = 1.0f / scale;
}

// ---------------- tensor-core GEMMs: R15 schedule, BK=128 (half the iters/bars) ----------------
// Row = 128 data bytes + 16 pad = 144 B = 36 ints. Fragment rows stride 4 banks;
// 8 rows x 4 consecutive banks = exact 32-bank cover -> conflict-free.
#define ASTR2 36
#define BUFI2 (128 * ASTR2)      // 4608 ints per tile
#define SSTG2 (2 * BUFI2)        // A + B per stage
#define GSM2  (2 * SSTG2 * 4)    // 73728 bytes dynamic smem

// GEMM1: h = xq @ w1q^T; block 128m x (64 up + 64 gate); 4 warps 2x2; K=768 -> 6 iters.
__global__ void __launch_bounds__(128) k_gemm1() {
    extern __shared__ int sh[];
    const int8_t* __restrict__ xq = g_xq;
    const int8_t* __restrict__ wq = g_w1q;
    int m0 = blockIdx.y << 7;
    int n0 = blockIdx.x << 6;
    int tid = threadIdx.x, lane = tid & 31, wid = tid >> 5;
    int wm = wid >> 1, wn = wid & 1;

    int acc[4][8][4];                      // [mt][nt: 0-3 up, 4-7 gate][c]
#pragma unroll
    for (int i = 0; i < 4; i++)
#pragma unroll
        for (int j = 0; j < 8; j++)
#pragma unroll
            for (int c = 0; c < 4; c++) acc[i][j][c] = 0;

#define G1_LOAD(IT, BUF)                                                        \
    {                                                                           \
        int k0 = (IT) * 128;                                                    \
        int* Ab = sh + (BUF) * SSTG2;                                           \
        int* Bb = Ab + BUFI2;                                                   \
        _Pragma("unroll")                                                       \
        for (int c = tid; c < 1024; c += 128) {                                 \
            int r = c >> 3, ck = c & 7;                                         \
            cp16(smem_u32(Ab + r * ASTR2 + ck * 4),                             \
                 xq + (size_t)(m0 + r) * DIM + k0 + ck * 16);                   \
            int nr = (r < 64) ? (n0 + r) : (HID + n0 + r - 64);                 \
            cp16(smem_u32(Bb + r * ASTR2 + ck * 4),                             \
                 wq + (size_t)nr * DIM + k0 + ck * 16);                         \
        }                                                                       \
    }

    G1_LOAD(0, 0); cp_commit();
#pragma unroll 1
    for (int it = 0; it < 6; it++) {
        if (it + 1 < 6) { G1_LOAD(it + 1, (it + 1) & 1); cp_commit(); cp_wait<1>(); }
        else cp_wait<0>();
        __syncthreads();
        int* Ab = sh + (it & 1) * SSTG2;
        int* Bb = Ab + BUFI2;
#pragma unroll
        for (int ks = 0; ks < 4; ks++) {
            int w = ks * 8 + (lane & 3);
            int a[4][4];
#pragma unroll
            for (int mt = 0; mt < 4; mt++) {
                int r = wm * 64 + mt * 16 + (lane >> 2);
                a[mt][0] = Ab[r * ASTR2 + w];
                a[mt][1] = Ab[(r + 8) * ASTR2 + w];
                a[mt][2] = Ab[r * ASTR2 + w + 4];
                a[mt][3] = Ab[(r + 8) * ASTR2 + w + 4];
            }
#pragma unroll
            for (int nt = 0; nt < 8; nt++) {
                int rn = ((nt < 4) ? (wn * 32 + nt * 8) : (64 + wn * 32 + (nt - 4) * 8))
                         + (lane >> 2);
                int b0 = Bb[rn * ASTR2 + w];
                int b1 = Bb[rn * ASTR2 + w + 4];
#pragma unroll
                for (int mt = 0; mt < 4; mt++)
                    mma_s8(acc[mt][nt], a[mt][0], a[mt][1], a[mt][2], a[mt][3], b0, b1);
            }
        }
        __syncthreads();
    }
#undef G1_LOAD

    // epilogue: swiglu + scale, write fp32 y
    float wdq = g_wdq[0];
#pragma unroll
    for (int mt = 0; mt < 4; mt++) {
        int r0 = m0 + wm * 64 + mt * 16 + (lane >> 2);
        float s0 = g_xdq[r0] * wdq;
        float s1 = g_xdq[r0 + 8] * wdq;
#pragma unroll
        for (int nt = 0; nt < 4; nt++) {
            int c = n0 + wn * 32 + nt * 8 + 2 * (lane & 3);
            int* u = acc[mt][nt];
            int* g = acc[mt][nt + 4];
            {
                float up0 = (float)u[0] * s0, gt0 = (float)g[0] * s0;
                float up1 = (float)u[1] * s0, gt1 = (float)g[1] * s0;
                float2 o;
                o.x = gt0 / (1.0f + expf(-gt0)) * up0;
                o.y = gt1 / (1.0f + expf(-gt1)) * up1;
                *(float2*)&g_y[(size_t)r0 * HID + c] = o;
            }
            {
                float up0 = (float)u[2] * s1, gt0 = (float)g[2] * s1;
                float up1 = (float)u[3] * s1, gt1 = (float)g[3] * s1;
                float2 o;
                o.x = gt0 / (1.0f + expf(-gt0)) * up0;
                o.y = gt1 / (1.0f + expf(-gt1)) * up1;
                *(float2*)&g_y[(size_t)(r0 + 8) * HID + c] = o;
            }
        }
    }
}

// GEMM2: out = yq @ w2q^T. Block 128x128, warps 2x2, warp 64x64; K=2048 -> 16 iters.
__global__ void __launch_bounds__(128) k_gemm2(float* __restrict__ out) {
    extern __shared__ int sh[];
    const int8_t* __restrict__ yq = g_yq;
    const int8_t* __restrict__ wq = g_w2q;
    int m0 = blockIdx.y << 7;
    int n0 = blockIdx.x << 7;
    int tid = threadIdx.x, lane = tid & 31, wid = tid >> 5;
    int wm = wid >> 1, wn = wid & 1;

    int acc[4][8][4];
#pragma unroll
    for (int i = 0; i < 4; i++)
#pragma unroll
        for (int j = 0; j < 8; j++)
#pragma unroll
            for (int c = 0; c < 4; c++) acc[i][j][c] = 0;

#define G2_LOAD(IT, BUF)                                                        \
    {                                                                           \
        int k0 = (IT) * 128;                                                    \
        int* Ab = sh + (BUF) * SSTG2;                                           \
        int* Bb = Ab + BUFI2;                                                   \
        _Pragma("unroll")                                                       \
        for (int c = tid; c < 1024; c += 128) {                                 \
            int r = c >> 3, ck = c & 7;                                         \
            cp16(smem_u32(Ab + r * ASTR2 + ck * 4),                             \
                 yq + (size_t)(m0 + r) * HID + k0 + ck * 16);                   \
            cp16(smem_u32(Bb + r * ASTR2 + ck * 4),                             \
                 wq + (size_t)(n0 + r) * HID + k0 + ck * 16);                   \
        }                                                                       \
    }

    G2_LOAD(0, 0); cp_commit();
#pragma unroll 1
    for (int it = 0; it < 16; it++) {
        if (it + 1 < 16) { G2_LOAD(it + 1, (it + 1) & 1); cp_commit(); cp_wait<1>(); }
        else cp_wait<0>();
        __syncthreads();
        int* Ab = sh + (it & 1) * SSTG2;
        int* Bb = Ab + BUFI2;
#pragma unroll
        for (int ks = 0; ks < 4; ks++) {
            int w = ks * 8 + (lane & 3);
            int a[4][4];
#pragma unroll
            for (int mt = 0; mt < 4; mt++) {
                int r = wm * 64 + mt * 16 + (lane >> 2);
                a[mt][0] = Ab[r * ASTR2 + w];
                a[mt][1] = Ab[(r + 8) * ASTR2 + w];
                a[mt][2] = Ab[r * ASTR2 + w + 4];
                a[mt][3] = Ab[(r + 8) * ASTR2 + w + 4];
            }
#pragma unroll
            for (int nt = 0; nt < 8; nt++) {
                int rn = wn * 64 + nt * 8 + (lane >> 2);
                int b0 = Bb[rn * ASTR2 + w];
                int b1 = Bb[rn * ASTR2 + w + 4];
#pragma unroll
                for (int mt = 0; mt < 4; mt++)
                    mma_s8(acc[mt][nt], a[mt][0], a[mt][1], a[mt][2], a[mt][3], b0, b1);
            }
        }
        __syncthreads();
    }
#undef G2_LOAD

    float wdq = g_wdq[1];
#pragma unroll
    for (int mt = 0; mt < 4; mt++) {
        int r0 = m0 + wm * 64 + mt * 16 + (lane >> 2);
        float s0 = g_ydq[r0] * wdq;
        float s1 = g_ydq[r0 + 8] * wdq;
#pragma unroll
        for (int nt = 0; nt < 8; nt++) {
            int c = n0 + wn * 64 + nt * 8 + 2 * (lane & 3);
            int* q = acc[mt][nt];
            float2 o0 = make_float2((float)q[0] * s0, (float)q[1] * s0);
            float2 o1 = make_float2((float)q[2] * s1, (float)q[3] * s1);
            *(float2*)&out[(size_t)r0 * DIM + c] = o0;
            *(float2*)&out[(size_t)(r0 + 8) * DIM + c] = o1;
        }
    }
}

// ---------------- eager init: absorb first-launch driver pool growth ----------------
namespace {
struct EagerInit {
    EagerInit() {
        cudaFree(0);
        cudaFuncSetAttribute(k_gemm1, cudaFuncAttributeMaxDynamicSharedMemorySize, GSM2);
        cudaFuncSetAttribute(k_gemm2, cudaFuncAttributeMaxDynamicSharedMemorySize, GSM2);
        void* py = nullptr; void* pdq = nullptr;
        cudaGetSymbolAddress(&py, g_y);
        cudaGetSymbolAddress(&pdq, g_xdq);
        const float* fy = (const float*)py;
        k_init<<<1, 1>>>();
        k_abssum<<<2, 256>>>(fy, 1024, 0);
        k_wquant<<<1, 256>>>(fy, 256, 0, 1.0);
        k_quant_x<<<1, 256>>>(fy, (const float*)pdq);
        k_quant_y<<<1, 256>>>((const float*)pdq);
        k_gemm1<<<dim3(1, 1), 128, GSM2>>>();
        k_gemm2<<<dim3(1, 1), 128, GSM2>>>((float*)py);
        cudaDeviceSynchronize();
        cudaGetLastError();
    }
};
EagerInit eager_init_;
}  // namespace

// ---------------- launch ----------------
extern "C" void kernel_launch(void* const* d_in, const int* in_sizes, int n_in,
                              void* d_out, int out_size) {
    const float* x = nullptr, *w_in = nullptr, *gin = nullptr,
               *w_out = nullptr, *gout = nullptr;
    for (int i = 0; i < n_in; i++) {
        long long s = in_sizes[i];
        if (s == 25165824LL || s == 100663296LL)      x     = (const float*)d_in[i];
        else if (s == 3145728LL || s == 12582912LL)   w_in  = (const float*)d_in[i];
        else if (s == 1572864LL || s == 6291456LL)    w_out = (const float*)d_in[i];
        else if (s == 768LL     || s == 3072LL)       gin   = (const float*)d_in[i];
        else if (s == 2048LL    || s == 8192LL)       gout  = (const float*)d_in[i];
    }
    if (!x || !w_in || !gin || !w_out || !gout) {
        int idx[16];
        int m = n_in < 16 ? n_in : 16;
        for (int i = 0; i < m; i++) idx[i] = i;
        for (int a = 0; a < m; a++)
            for (int b = a + 1; b < m; b++)
                if ((long long)in_sizes[idx[b]] < (long long)in_sizes[idx[a]]) {
                    int t = idx[a]; idx[a] = idx[b]; idx[b] = t;
                }
        gin   = (const float*)d_in[idx[0]];
        gout  = (const float*)d_in[idx[1]];
        w_out = (const float*)d_in[idx[2]];
        w_in  = (const float*)d_in[idx[3]];
        x     = (const float*)d_in[idx[4]];
    }
    float* out = (float*)d_out;

    k_init<<<1, 1>>>();
    k_abssum<<<512, 256>>>(w_in,  N1 * DIM, 0);
    k_abssum<<<512, 256>>>(w_out, DIM * HID, 1);

    k_wquant<<<(N1 * DIM / 4 + 255) / 256, 256>>>(w_in,  N1 * DIM / 4, 0,
                                                  1.0 / (double)(N1 * DIM));
    k_wquant<<<(DIM * HID / 4 + 255) / 256, 256>>>(w_out, DIM * HID / 4, 1,
                                                   1.0 / (double)(DIM * HID));

    k_quant_x<<<TKN / 8, 256>>>(x, gin);          // warp-per-token

    k_gemm1<<<dim3(HID / 64, TKN / 128), 128, GSM2>>>();

    k_quant_y<<<TKN / 8, 256>>>(gout);            // warp-per-token

    k_gemm2<<<dim3(DIM / 128, TKN / 128), 128, GSM2>>>(out);
}